// round 14
// baseline (speedup 1.0000x reference)
#include <cuda_runtime.h>
#include <cstdint>

#define N_TOK 8192
#define EMB 1024
#define HID 4096
#define NE 8
#define GAP_THR 2e-3f

// ---------------- device scratch (no allocations allowed) ----------------
// NEVER pass these as kernel arguments from host code (ATS host-shadow bug).
__device__ float g_H[(size_t)N_TOK * EMB];        // router hidden (bf16x3 approx)
__device__ float g_Hfix[(size_t)N_TOK * EMB];     // exact hidden rows for suspects
__device__ float g_hidden[(size_t)N_TOK * HID];   // expert hidden (permuted rows)
__device__ int   g_chosen[N_TOK];
__device__ int   g_counts[NE];
__device__ int   g_offsets[NE + 1];
__device__ int   g_cursor[NE];
__device__ int   g_perm[N_TOK];
__device__ int   g_suspects[N_TOK];
__device__ int   g_nsus;

// ---------------- helpers ----------------
__device__ __forceinline__ uint32_t smem_u32(const void* p) {
    uint32_t a;
    asm("{ .reg .u64 t; cvta.to.shared.u64 t, %1; cvt.u32.u64 %0, t; }" : "=r"(a) : "l"(p));
    return a;
}
__device__ __forceinline__ void ldsm_x4(uint32_t& r0, uint32_t& r1, uint32_t& r2, uint32_t& r3,
                                        uint32_t addr) {
    asm volatile("ldmatrix.sync.aligned.m8n8.x4.shared.b16 {%0,%1,%2,%3}, [%4];"
                 : "=r"(r0), "=r"(r1), "=r"(r2), "=r"(r3) : "r"(addr));
}
__device__ __forceinline__ void mma_bf16(float* c, const uint32_t* a, const uint32_t* b) {
    asm volatile(
        "mma.sync.aligned.m16n8k16.row.col.f32.bf16.bf16.f32 "
        "{%0,%1,%2,%3}, {%4,%5,%6,%7}, {%8,%9}, {%0,%1,%2,%3};"
        : "+f"(c[0]), "+f"(c[1]), "+f"(c[2]), "+f"(c[3])
        : "r"(a[0]), "r"(a[1]), "r"(a[2]), "r"(a[3]), "r"(b[0]), "r"(b[1]));
}
__device__ __forceinline__ uint32_t bf16x2(float x, float y) {  // x->low, y->high
    uint32_t r;
    asm("cvt.rn.bf16x2.f32 %0, %1, %2;" : "=r"(r) : "f"(y), "f"(x));
    return r;
}
__device__ __forceinline__ void split_pair(float x, float y, uint32_t& hi, uint32_t& lo) {
    hi = bf16x2(x, y);
    float hx = __uint_as_float(hi << 16);
    float hy = __uint_as_float(hi & 0xFFFF0000u);
    lo = bf16x2(x - hx, y - hy);
}
__device__ __forceinline__ void sts_v4(uint32_t addr, uint32_t a, uint32_t b, uint32_t c, uint32_t d) {
    asm volatile("st.shared.v4.b32 [%0], {%1,%2,%3,%4};" :: "r"(addr), "r"(a), "r"(b), "r"(c), "r"(d) : "memory");
}

// packed f32x2 (exact fixup GEMM)
__device__ __forceinline__ uint64_t pk2(float x, float y) {
    uint64_t r;
    asm("mov.b64 %0, {%1, %2};" : "=l"(r) : "f"(x), "f"(y));
    return r;
}
__device__ __forceinline__ void ffma2(uint64_t& d, uint64_t a, uint64_t b) {
    asm("fma.rn.f32x2 %0, %1, %2, %0;" : "+l"(d) : "l"(a), "l"(b));
}
__device__ __forceinline__ void unpk2(uint64_t v, float& x, float& y) {
    asm("mov.b64 {%0, %1}, %2;" : "=f"(x), "=f"(y) : "l"(v));
}
#define FFMA2_KK_STEP(accp, a, b) do {                                   \
    uint64_t _a2[4], _b2[8];                                             \
    _a2[0] = pk2((a)[0], (a)[1]); _a2[1] = pk2((a)[2], (a)[3]);          \
    _a2[2] = pk2((a)[4], (a)[5]); _a2[3] = pk2((a)[6], (a)[7]);          \
    _b2[0] = pk2((b)[0], (b)[0]); _b2[1] = pk2((b)[1], (b)[1]);          \
    _b2[2] = pk2((b)[2], (b)[2]); _b2[3] = pk2((b)[3], (b)[3]);          \
    _b2[4] = pk2((b)[4], (b)[4]); _b2[5] = pk2((b)[5], (b)[5]);          \
    _b2[6] = pk2((b)[6], (b)[6]); _b2[7] = pk2((b)[7], (b)[7]);          \
    _Pragma("unroll")                                                    \
    for (int _i = 0; _i < 4; _i++)                                       \
        _Pragma("unroll")                                                \
        for (int _j = 0; _j < 8; _j++) ffma2((accp)[_i][_j], _a2[_i], _b2[_j]); \
} while (0)

// SMEM stage layout (bf16, row stride 40 elems = 80 B, conflict-free):
// A_hi [0,10240) | A_lo [10240,20480) | B_hi [20480,40960) | B_lo [40960,61440)
#define RS 40
#define OFF_ALO 10240u
#define OFF_BHI 20480u
#define OFF_BLO 40960u
#define STAGE 61440u
#define FFN_SMEM (2 * 61440)

// ============================================================================
// bf16x3 mma.sync GEMM (verified R12/R13). CTA tile 128x256, BK=32, 8 warps 64x64.
// SRC: 0=Ain param, 1=g_hidden. DST: 0=Cout param, 1=g_hidden, 2=g_H.
// ============================================================================
template <int NTOT, int KTOT, bool EXPERT, bool GATHER, bool RELU, bool SCATTER,
          int SRC, int DST>
__global__ __launch_bounds__(256, 1) void ffn_mma(
    const float* __restrict__ Ain, const float* __restrict__ Bw,
    const float* __restrict__ biasw, float* __restrict__ Cout)
{
    extern __shared__ __align__(16) uint8_t smem[];
    const float* A = (SRC == 1) ? (const float*)g_hidden : Ain;
    float* C = (DST == 1) ? (float*)g_hidden : ((DST == 2) ? (float*)g_H : Cout);

    int e = 0, start = 0, end = N_TOK;
    if (EXPERT) { e = blockIdx.z; start = g_offsets[e]; end = g_offsets[e + 1]; }
    const int m0 = start + blockIdx.x * 128;
    if (m0 >= end) return;
    const int n0 = blockIdx.y * 256;
    const float* Bm = Bw + (size_t)e * KTOT * NTOT;
    const uint32_t sb = smem_u32(smem);

    const int tid = threadIdx.x, wid = tid >> 5, lane = tid & 31;
    const int wm = wid & 1, wn = wid >> 1, qid = lane >> 2, tig = lane & 3;

    // A loader
    const int ar = tid >> 1;
    const int akc = (tid & 1) * 16;
    int rld = m0 + ar;
    int rc = (rld < end) ? rld : start;
    int grow = GATHER ? g_perm[rc] : rc;
    const float* Ap = A + (size_t)grow * KTOT + akc;
    const uint32_t a_sts = (uint32_t)(ar * RS + akc) * 2;

    // B loader: k-group = (tid>>6)*8, n = (tid&63) + 64j
    const int bk = (tid >> 6) * 8;
    const int bn = tid & 63;
    const float* Bp = Bm + n0 + bn;
    const uint32_t b_sts0 = (uint32_t)(bn * RS + bk) * 2;

    uint32_t a_ldm[4];
#pragma unroll
    for (int mt = 0; mt < 4; mt++)
        a_ldm[mt] = (uint32_t)((wm * 64 + mt * 16 + (lane & 15)) * RS) * 2 +
                    ((lane >> 4) & 1) * 16;
    uint32_t b_ldm[4];
#pragma unroll
    for (int p = 0; p < 4; p++)
        b_ldm[p] = OFF_BHI +
                   (uint32_t)((wn * 64 + p * 16 + (lane & 7) + ((lane >> 4) & 1) * 8) * RS) * 2 +
                   ((lane >> 3) & 1) * 16;

    float acc[4][8][4];
#pragma unroll
    for (int mt = 0; mt < 4; mt++)
#pragma unroll
        for (int nt = 0; nt < 8; nt++)
#pragma unroll
            for (int i = 0; i < 4; i++) acc[mt][nt][i] = 0.f;

    float4 av[4];
    float bv[8][4];
    const int NC = KTOT / 32;

#pragma unroll
    for (int i = 0; i < 4; i++) av[i] = *(const float4*)(Ap + 4 * i);
#pragma unroll
    for (int i = 0; i < 8; i++) {
        const float* rowp = Bp + (size_t)(bk + i) * NTOT;
#pragma unroll
        for (int j = 0; j < 4; j++) bv[i][j] = rowp[64 * j];
    }
    {
        uint32_t h[8], l[8];
#pragma unroll
        for (int i = 0; i < 4; i++) {
            split_pair(av[i].x, av[i].y, h[2 * i + 0], l[2 * i + 0]);
            split_pair(av[i].z, av[i].w, h[2 * i + 1], l[2 * i + 1]);
        }
        sts_v4(sb + a_sts, h[0], h[1], h[2], h[3]);
        sts_v4(sb + a_sts + 16, h[4], h[5], h[6], h[7]);
        sts_v4(sb + OFF_ALO + a_sts, l[0], l[1], l[2], l[3]);
        sts_v4(sb + OFF_ALO + a_sts + 16, l[4], l[5], l[6], l[7]);
#pragma unroll
        for (int j = 0; j < 4; j++) {
            uint32_t bh[4], bl[4];
            split_pair(bv[0][j], bv[1][j], bh[0], bl[0]);
            split_pair(bv[2][j], bv[3][j], bh[1], bl[1]);
            split_pair(bv[4][j], bv[5][j], bh[2], bl[2]);
            split_pair(bv[6][j], bv[7][j], bh[3], bl[3]);
            sts_v4(sb + OFF_BHI + b_sts0 + j * 5120, bh[0], bh[1], bh[2], bh[3]);
            sts_v4(sb + OFF_BLO + b_sts0 + j * 5120, bl[0], bl[1], bl[2], bl[3]);
        }
    }
    __syncthreads();

#pragma unroll 1
    for (int kc = 0; kc < NC; kc++) {
        if (kc + 1 < NC) {
            const int k0 = (kc + 1) * 32;
#pragma unroll
            for (int i = 0; i < 4; i++) av[i] = *(const float4*)(Ap + k0 + 4 * i);
#pragma unroll
            for (int i = 0; i < 8; i++) {
                const float* rowp = Bp + (size_t)(k0 + bk + i) * NTOT;
#pragma unroll
                for (int j = 0; j < 4; j++) bv[i][j] = rowp[64 * j];
            }
        }
        const uint32_t cur = sb + (uint32_t)(kc & 1) * STAGE;
#pragma unroll
        for (int ks = 0; ks < 2; ks++) {
            uint32_t ah[4][4], al[4][4];
#pragma unroll
            for (int mt = 0; mt < 4; mt++) {
                const uint32_t ab = cur + a_ldm[mt] + ks * 32;
                ldsm_x4(ah[mt][0], ah[mt][1], ah[mt][2], ah[mt][3], ab);
                ldsm_x4(al[mt][0], al[mt][1], al[mt][2], al[mt][3], ab + OFF_ALO);
            }
#pragma unroll
            for (int p = 0; p < 4; p++) {
                const uint32_t bb = cur + b_ldm[p] + ks * 32;
                uint32_t bh[4], bl[4];
                ldsm_x4(bh[0], bh[1], bh[2], bh[3], bb);
                ldsm_x4(bl[0], bl[1], bl[2], bl[3], bb + (OFF_BLO - OFF_BHI));
#pragma unroll
                for (int mt = 0; mt < 4; mt++) {
                    mma_bf16(acc[mt][2 * p + 0], ah[mt], &bh[0]);
                    mma_bf16(acc[mt][2 * p + 0], ah[mt], &bl[0]);
                    mma_bf16(acc[mt][2 * p + 0], al[mt], &bh[0]);
                    mma_bf16(acc[mt][2 * p + 1], ah[mt], &bh[2]);
                    mma_bf16(acc[mt][2 * p + 1], ah[mt], &bl[2]);
                    mma_bf16(acc[mt][2 * p + 1], al[mt], &bh[2]);
                }
            }
        }
        if (kc + 1 < NC) {
            const uint32_t nxt = sb + (uint32_t)((kc + 1) & 1) * STAGE;
            uint32_t h[8], l[8];
#pragma unroll
            for (int i = 0; i < 4; i++) {
                split_pair(av[i].x, av[i].y, h[2 * i + 0], l[2 * i + 0]);
                split_pair(av[i].z, av[i].w, h[2 * i + 1], l[2 * i + 1]);
            }
            sts_v4(nxt + a_sts, h[0], h[1], h[2], h[3]);
            sts_v4(nxt + a_sts + 16, h[4], h[5], h[6], h[7]);
            sts_v4(nxt + OFF_ALO + a_sts, l[0], l[1], l[2], l[3]);
            sts_v4(nxt + OFF_ALO + a_sts + 16, l[4], l[5], l[6], l[7]);
#pragma unroll
            for (int j = 0; j < 4; j++) {
                uint32_t bh[4], bl[4];
                split_pair(bv[0][j], bv[1][j], bh[0], bl[0]);
                split_pair(bv[2][j], bv[3][j], bh[1], bl[1]);
                split_pair(bv[4][j], bv[5][j], bh[2], bl[2]);
                split_pair(bv[6][j], bv[7][j], bh[3], bl[3]);
                sts_v4(nxt + OFF_BHI + b_sts0 + j * 5120, bh[0], bh[1], bh[2], bh[3]);
                sts_v4(nxt + OFF_BLO + b_sts0 + j * 5120, bl[0], bl[1], bl[2], bl[3]);
            }
        }
        __syncthreads();
    }

    // ---- epilogue ----
    const float* bs = biasw + (size_t)e * NTOT;
    const int trow = qid, tcol = tig * 2;
    float2 bb2[8];
#pragma unroll
    for (int nt = 0; nt < 8; nt++) {
        int col = n0 + wn * 64 + nt * 8 + tcol;
        bb2[nt] = *(const float2*)(bs + col);
    }
#pragma unroll
    for (int mt = 0; mt < 4; mt++) {
        int r0 = m0 + wm * 64 + mt * 16 + trow;
        int r1 = r0 + 8;
        bool v0 = r0 < end, v1 = r1 < end;
        int c0 = SCATTER ? (v0 ? g_perm[r0] : 0) : r0;
        int c1 = SCATTER ? (v1 ? g_perm[r1] : 0) : r1;
        float* p0 = C + (size_t)c0 * NTOT + n0 + wn * 64 + tcol;
        float* p1 = C + (size_t)c1 * NTOT + n0 + wn * 64 + tcol;
#pragma unroll
        for (int nt = 0; nt < 8; nt++) {
            float2 o0, o1;
            o0.x = acc[mt][nt][0] + bb2[nt].x;
            o0.y = acc[mt][nt][1] + bb2[nt].y;
            o1.x = acc[mt][nt][2] + bb2[nt].x;
            o1.y = acc[mt][nt][3] + bb2[nt].y;
            if (RELU) {
                o0.x = fmaxf(o0.x, 0.f); o0.y = fmaxf(o0.y, 0.f);
                o1.x = fmaxf(o1.x, 0.f); o1.y = fmaxf(o1.y, 0.f);
            }
            if (v0) *(float2*)(p0 + nt * 8) = o0;
            if (v1) *(float2*)(p1 + nt * 8) = o1;
        }
    }
}

// ---------------- router argmax + gap-based suspect detection ----------------
__global__ void init_counts()
{
    if (threadIdx.x < NE) g_counts[threadIdx.x] = 0;
    if (threadIdx.x == 0) g_nsus = 0;
}

__global__ __launch_bounds__(256)
void router_argmax(const float* __restrict__ Wr2, const float* __restrict__ br2)
{
    int gid = blockIdx.x * blockDim.x + threadIdx.x;
    int t = gid >> 5;
    int lane = gid & 31;
    if (t >= N_TOK) return;
    const float* h = g_H + (size_t)t * EMB;
    float acc[NE];
#pragma unroll
    for (int e = 0; e < NE; e++) acc[e] = 0.f;
    for (int i = lane; i < EMB; i += 32) {
        float hv = h[i];
        const float4 w0 = *(const float4*)(Wr2 + (size_t)i * NE);
        const float4 w1 = *(const float4*)(Wr2 + (size_t)i * NE + 4);
        acc[0] = fmaf(hv, w0.x, acc[0]);
        acc[1] = fmaf(hv, w0.y, acc[1]);
        acc[2] = fmaf(hv, w0.z, acc[2]);
        acc[3] = fmaf(hv, w0.w, acc[3]);
        acc[4] = fmaf(hv, w1.x, acc[4]);
        acc[5] = fmaf(hv, w1.y, acc[5]);
        acc[6] = fmaf(hv, w1.z, acc[6]);
        acc[7] = fmaf(hv, w1.w, acc[7]);
    }
#pragma unroll
    for (int off = 16; off > 0; off >>= 1)
#pragma unroll
        for (int e = 0; e < NE; e++)
            acc[e] += __shfl_xor_sync(0xffffffffu, acc[e], off);
    if (lane == 0) {
        int best = 0;
        float bv = acc[0] + br2[0], sv = -3.4e38f;
#pragma unroll
        for (int e = 1; e < NE; e++) {
            float v = acc[e] + br2[e];
            if (v > bv) { sv = bv; bv = v; best = e; }
            else if (v > sv) sv = v;
        }
        g_chosen[t] = best;
        if (bv - sv < GAP_THR) {
            int pos = atomicAdd(&g_nsus, 1);
            g_suspects[pos] = t;
        }
    }
}

// ---------------- batched exact fixup: g_Hfix[si] = relu(x[suspect si] @ Wr1 + br1)
// Exact fp32 FFMA2 GEMM (round-6 verified math), rows gathered from g_suspects,
// dynamic row count g_nsus; idle CTAs exit immediately.
__global__ __launch_bounds__(256, 2)
void sgemm_fix(const float* __restrict__ A, const float* __restrict__ B,
               const float* __restrict__ bias)
{
    const int K = EMB, N = EMB;
    const int ns = g_nsus;
    const int m0 = blockIdx.x * 128;
    if (m0 >= ns) return;
    __shared__ float As[8][128];
    __shared__ float Bs[8][128];
    const int tid = threadIdx.x;
    const int n0 = blockIdx.y * 128;
    const int arow = tid >> 1;
    const int acol = (tid & 1) * 4;
    const int brow = tid >> 5;
    const int bcol = (tid & 31) * 4;
    int r = m0 + arow;
    int rc = (r < ns) ? r : (ns - 1);
    int tok = g_suspects[rc];
    const float* Ap = A + (size_t)tok * K + acol;
    const float* Bp = B + (size_t)brow * N + n0 + bcol;
    const int ty = (tid >> 4) * 8;
    const int tx = (tid & 15) * 8;
    uint64_t accp[4][8];
#pragma unroll
    for (int i = 0; i < 4; i++)
#pragma unroll
        for (int j = 0; j < 8; j++) accp[i][j] = 0ull;

    for (int k0 = 0; k0 < K; k0 += 8) {
        float4 av = *(const float4*)(Ap + k0);
        float4 bv = *(const float4*)(Bp + (size_t)k0 * N);
        As[acol + 0][arow] = av.x;
        As[acol + 1][arow] = av.y;
        As[acol + 2][arow] = av.z;
        As[acol + 3][arow] = av.w;
        *(float4*)&Bs[brow][bcol] = bv;
        __syncthreads();
#pragma unroll
        for (int kk = 0; kk < 8; kk++) {
            float a[8], b[8];
            *(float4*)&a[0] = *(const float4*)&As[kk][ty];
            *(float4*)&a[4] = *(const float4*)&As[kk][ty + 4];
            *(float4*)&b[0] = *(const float4*)&Bs[kk][tx];
            *(float4*)&b[4] = *(const float4*)&Bs[kk][tx + 4];
            FFMA2_KK_STEP(accp, a, b);
        }
        __syncthreads();
    }
    float acc[8][8];
#pragma unroll
    for (int i2 = 0; i2 < 4; i2++)
#pragma unroll
        for (int j = 0; j < 8; j++) unpk2(accp[i2][j], acc[2 * i2][j], acc[2 * i2 + 1][j]);
#pragma unroll
    for (int i = 0; i < 8; i++) {
        int rr = m0 + ty + i;
        if (rr < ns) {
            float* Cp = g_Hfix + (size_t)rr * N + n0 + tx;
#pragma unroll
            for (int j = 0; j < 8; j += 4) {
                float4 v;
                v.x = fmaxf(acc[i][j + 0] + bias[n0 + tx + j + 0], 0.f);
                v.y = fmaxf(acc[i][j + 1] + bias[n0 + tx + j + 1], 0.f);
                v.z = fmaxf(acc[i][j + 2] + bias[n0 + tx + j + 2], 0.f);
                v.w = fmaxf(acc[i][j + 3] + bias[n0 + tx + j + 3], 0.f);
                *(float4*)(Cp + j) = v;
            }
        }
    }
}

// exact logits + argmax on suspect rows (warp per suspect)
__global__ __launch_bounds__(256)
void fixup_logits(const float* __restrict__ Wr2, const float* __restrict__ br2)
{
    int gid = blockIdx.x * blockDim.x + threadIdx.x;
    int si = gid >> 5;
    int lane = gid & 31;
    if (si >= g_nsus) return;
    const float* h = g_Hfix + (size_t)si * EMB;
    float acc[NE];
#pragma unroll
    for (int e = 0; e < NE; e++) acc[e] = 0.f;
    for (int i = lane; i < EMB; i += 32) {
        float hv = h[i];
        const float4 w0 = *(const float4*)(Wr2 + (size_t)i * NE);
        const float4 w1 = *(const float4*)(Wr2 + (size_t)i * NE + 4);
        acc[0] = fmaf(hv, w0.x, acc[0]);
        acc[1] = fmaf(hv, w0.y, acc[1]);
        acc[2] = fmaf(hv, w0.z, acc[2]);
        acc[3] = fmaf(hv, w0.w, acc[3]);
        acc[4] = fmaf(hv, w1.x, acc[4]);
        acc[5] = fmaf(hv, w1.y, acc[5]);
        acc[6] = fmaf(hv, w1.z, acc[6]);
        acc[7] = fmaf(hv, w1.w, acc[7]);
    }
#pragma unroll
    for (int off = 16; off > 0; off >>= 1)
#pragma unroll
        for (int e = 0; e < NE; e++)
            acc[e] += __shfl_xor_sync(0xffffffffu, acc[e], off);
    if (lane == 0) {
        int best = 0;
        float bv = acc[0] + br2[0];
#pragma unroll
        for (int e = 1; e < NE; e++) {
            float v = acc[e] + br2[e];
            if (v > bv) { bv = v; best = e; }
        }
        g_chosen[g_suspects[si]] = best;
    }
}

__global__ void count_tokens()
{
    int t = blockIdx.x * blockDim.x + threadIdx.x;
    if (t < N_TOK) atomicAdd(&g_counts[g_chosen[t]], 1);
}

__global__ void scan_offsets()
{
    if (threadIdx.x == 0 && blockIdx.x == 0) {
        int o = 0;
        for (int e = 0; e < NE; e++) {
            g_offsets[e] = o;
            g_cursor[e] = o;
            o += g_counts[e];
        }
        g_offsets[NE] = o;
    }
}

__global__ void scatter_tokens()
{
    int t = blockIdx.x * blockDim.x + threadIdx.x;
    if (t >= N_TOK) return;
    int e = g_chosen[t];
    int pos = atomicAdd(&g_cursor[e], 1);
    g_perm[pos] = t;
}

// ---------------- launch ----------------
extern "C" void kernel_launch(void* const* d_in, const int* in_sizes, int n_in,
                              void* d_out, int out_size)
{
    const float* x   = (const float*)d_in[0];
    const float* Wr1 = (const float*)d_in[1];
    const float* br1 = (const float*)d_in[2];
    const float* Wr2 = (const float*)d_in[3];
    const float* br2 = (const float*)d_in[4];
    const float* W1  = (const float*)d_in[5];
    const float* b1  = (const float*)d_in[6];
    const float* W2  = (const float*)d_in[7];
    const float* b2  = (const float*)d_in[8];
    float* out = (float*)d_out;

    auto* kRouter = ffn_mma<EMB, EMB, false, false, true, false, 0, 2>;
    auto* kFfn1   = ffn_mma<HID, EMB, true, true, true, false, 0, 1>;
    auto* kFfn2   = ffn_mma<EMB, HID, true, false, false, true, 1, 0>;
    cudaFuncSetAttribute(kRouter, cudaFuncAttributeMaxDynamicSharedMemorySize, FFN_SMEM);
    cudaFuncSetAttribute(kFfn1, cudaFuncAttributeMaxDynamicSharedMemorySize, FFN_SMEM);
    cudaFuncSetAttribute(kFfn2, cudaFuncAttributeMaxDynamicSharedMemorySize, FFN_SMEM);

    init_counts<<<1, 32>>>();
    kRouter<<<dim3(N_TOK / 128, EMB / 256, 1), 256, FFN_SMEM>>>(x, Wr1, br1, nullptr);
    router_argmax<<<(N_TOK * 32) / 256, 256>>>(Wr2, br2);
    // batched exact fixup (idle CTAs exit against g_nsus)
    sgemm_fix<<<dim3(N_TOK / 128, EMB / 128), 256>>>(x, Wr1, br1);
    fixup_logits<<<(N_TOK * 32) / 256, 256>>>(Wr2, br2);
    count_tokens<<<N_TOK / 256, 256>>>();
    scan_offsets<<<1, 1>>>();
    scatter_tokens<<<N_TOK / 256, 256>>>();
    kFfn1<<<dim3(N_TOK / 128, HID / 256, NE), 256, FFN_SMEM>>>(x, W1, b1, nullptr);
    kFfn2<<<dim3(N_TOK / 128, EMB / 256, NE), 256, FFN_SMEM>>>(nullptr, W2, b2, out);
}

// round 15
// speedup vs baseline: 1.5743x; 1.5743x over previous
#include <cuda_runtime.h>
#include <cstdint>

#define N_TOK 8192
#define EMB 1024
#define HID 4096
#define NE 8
#define GAP_THR 4e-4f

// ---------------- device scratch (no allocations allowed) ----------------
// NEVER pass these as kernel arguments from host code (ATS host-shadow bug).
__device__ float g_H[(size_t)N_TOK * EMB];        // router hidden (bf16x3 approx)
__device__ float g_hidden[(size_t)N_TOK * HID];   // expert hidden (permuted rows)
__device__ int   g_chosen[N_TOK];
__device__ int   g_counts[NE];
__device__ int   g_offsets[NE + 1];
__device__ int   g_cursor[NE];
__device__ int   g_perm[N_TOK];
__device__ int   g_suspects[N_TOK];
__device__ int   g_nsus;

// ---------------- helpers ----------------
__device__ __forceinline__ uint32_t smem_u32(const void* p) {
    uint32_t a;
    asm("{ .reg .u64 t; cvta.to.shared.u64 t, %1; cvt.u32.u64 %0, t; }" : "=r"(a) : "l"(p));
    return a;
}
__device__ __forceinline__ void ldsm_x4(uint32_t& r0, uint32_t& r1, uint32_t& r2, uint32_t& r3,
                                        uint32_t addr) {
    asm volatile("ldmatrix.sync.aligned.m8n8.x4.shared.b16 {%0,%1,%2,%3}, [%4];"
                 : "=r"(r0), "=r"(r1), "=r"(r2), "=r"(r3) : "r"(addr));
}
__device__ __forceinline__ void mma_bf16(float* c, const uint32_t* a, const uint32_t* b) {
    asm volatile(
        "mma.sync.aligned.m16n8k16.row.col.f32.bf16.bf16.f32 "
        "{%0,%1,%2,%3}, {%4,%5,%6,%7}, {%8,%9}, {%0,%1,%2,%3};"
        : "+f"(c[0]), "+f"(c[1]), "+f"(c[2]), "+f"(c[3])
        : "r"(a[0]), "r"(a[1]), "r"(a[2]), "r"(a[3]), "r"(b[0]), "r"(b[1]));
}
__device__ __forceinline__ uint32_t bf16x2(float x, float y) {  // x->low, y->high
    uint32_t r;
    asm("cvt.rn.bf16x2.f32 %0, %1, %2;" : "=r"(r) : "f"(y), "f"(x));
    return r;
}
__device__ __forceinline__ void split_pair(float x, float y, uint32_t& hi, uint32_t& lo) {
    hi = bf16x2(x, y);
    float hx = __uint_as_float(hi << 16);
    float hy = __uint_as_float(hi & 0xFFFF0000u);
    lo = bf16x2(x - hx, y - hy);
}
__device__ __forceinline__ void sts_v4(uint32_t addr, uint32_t a, uint32_t b, uint32_t c, uint32_t d) {
    asm volatile("st.shared.v4.b32 [%0], {%1,%2,%3,%4};" :: "r"(addr), "r"(a), "r"(b), "r"(c), "r"(d) : "memory");
}

// SMEM stage layout (bf16, row stride 40 elems = 80 B, conflict-free):
// A_hi [0,10240) | A_lo [10240,20480) | B_hi [20480,40960) | B_lo [40960,61440)
#define RS 40
#define OFF_ALO 10240u
#define OFF_BHI 20480u
#define OFF_BLO 40960u
#define STAGE 61440u
#define FFN_SMEM (2 * 61440)

// ============================================================================
// bf16x3 mma.sync GEMM (verified R12/R13). CTA tile 128x256, BK=32, 8 warps 64x64.
// SRC: 0=Ain param, 1=g_hidden. DST: 0=Cout param, 1=g_hidden, 2=g_H.
// ============================================================================
template <int NTOT, int KTOT, bool EXPERT, bool GATHER, bool RELU, bool SCATTER,
          int SRC, int DST>
__global__ __launch_bounds__(256, 1) void ffn_mma(
    const float* __restrict__ Ain, const float* __restrict__ Bw,
    const float* __restrict__ biasw, float* __restrict__ Cout)
{
    extern __shared__ __align__(16) uint8_t smem[];
    const float* A = (SRC == 1) ? (const float*)g_hidden : Ain;
    float* C = (DST == 1) ? (float*)g_hidden : ((DST == 2) ? (float*)g_H : Cout);

    int e = 0, start = 0, end = N_TOK;
    if (EXPERT) { e = blockIdx.z; start = g_offsets[e]; end = g_offsets[e + 1]; }
    const int m0 = start + blockIdx.x * 128;
    if (m0 >= end) return;
    const int n0 = blockIdx.y * 256;
    const float* Bm = Bw + (size_t)e * KTOT * NTOT;
    const uint32_t sb = smem_u32(smem);

    const int tid = threadIdx.x, wid = tid >> 5, lane = tid & 31;
    const int wm = wid & 1, wn = wid >> 1, qid = lane >> 2, tig = lane & 3;

    // A loader
    const int ar = tid >> 1;
    const int akc = (tid & 1) * 16;
    int rld = m0 + ar;
    int rc = (rld < end) ? rld : start;
    int grow = GATHER ? g_perm[rc] : rc;
    const float* Ap = A + (size_t)grow * KTOT + akc;
    const uint32_t a_sts = (uint32_t)(ar * RS + akc) * 2;

    // B loader: k-group = (tid>>6)*8, n = (tid&63) + 64j
    const int bk = (tid >> 6) * 8;
    const int bn = tid & 63;
    const float* Bp = Bm + n0 + bn;
    const uint32_t b_sts0 = (uint32_t)(bn * RS + bk) * 2;

    uint32_t a_ldm[4];
#pragma unroll
    for (int mt = 0; mt < 4; mt++)
        a_ldm[mt] = (uint32_t)((wm * 64 + mt * 16 + (lane & 15)) * RS) * 2 +
                    ((lane >> 4) & 1) * 16;
    uint32_t b_ldm[4];
#pragma unroll
    for (int p = 0; p < 4; p++)
        b_ldm[p] = OFF_BHI +
                   (uint32_t)((wn * 64 + p * 16 + (lane & 7) + ((lane >> 4) & 1) * 8) * RS) * 2 +
                   ((lane >> 3) & 1) * 16;

    float acc[4][8][4];
#pragma unroll
    for (int mt = 0; mt < 4; mt++)
#pragma unroll
        for (int nt = 0; nt < 8; nt++)
#pragma unroll
            for (int i = 0; i < 4; i++) acc[mt][nt][i] = 0.f;

    float4 av[4];
    float bv[8][4];
    const int NC = KTOT / 32;

#pragma unroll
    for (int i = 0; i < 4; i++) av[i] = *(const float4*)(Ap + 4 * i);
#pragma unroll
    for (int i = 0; i < 8; i++) {
        const float* rowp = Bp + (size_t)(bk + i) * NTOT;
#pragma unroll
        for (int j = 0; j < 4; j++) bv[i][j] = rowp[64 * j];
    }
    {
        uint32_t h[8], l[8];
#pragma unroll
        for (int i = 0; i < 4; i++) {
            split_pair(av[i].x, av[i].y, h[2 * i + 0], l[2 * i + 0]);
            split_pair(av[i].z, av[i].w, h[2 * i + 1], l[2 * i + 1]);
        }
        sts_v4(sb + a_sts, h[0], h[1], h[2], h[3]);
        sts_v4(sb + a_sts + 16, h[4], h[5], h[6], h[7]);
        sts_v4(sb + OFF_ALO + a_sts, l[0], l[1], l[2], l[3]);
        sts_v4(sb + OFF_ALO + a_sts + 16, l[4], l[5], l[6], l[7]);
#pragma unroll
        for (int j = 0; j < 4; j++) {
            uint32_t bh[4], bl[4];
            split_pair(bv[0][j], bv[1][j], bh[0], bl[0]);
            split_pair(bv[2][j], bv[3][j], bh[1], bl[1]);
            split_pair(bv[4][j], bv[5][j], bh[2], bl[2]);
            split_pair(bv[6][j], bv[7][j], bh[3], bl[3]);
            sts_v4(sb + OFF_BHI + b_sts0 + j * 5120, bh[0], bh[1], bh[2], bh[3]);
            sts_v4(sb + OFF_BLO + b_sts0 + j * 5120, bl[0], bl[1], bl[2], bl[3]);
        }
    }
    __syncthreads();

#pragma unroll 1
    for (int kc = 0; kc < NC; kc++) {
        if (kc + 1 < NC) {
            const int k0 = (kc + 1) * 32;
#pragma unroll
            for (int i = 0; i < 4; i++) av[i] = *(const float4*)(Ap + k0 + 4 * i);
#pragma unroll
            for (int i = 0; i < 8; i++) {
                const float* rowp = Bp + (size_t)(k0 + bk + i) * NTOT;
#pragma unroll
                for (int j = 0; j < 4; j++) bv[i][j] = rowp[64 * j];
            }
        }
        const uint32_t cur = sb + (uint32_t)(kc & 1) * STAGE;
#pragma unroll
        for (int ks = 0; ks < 2; ks++) {
            uint32_t ah[4][4], al[4][4];
#pragma unroll
            for (int mt = 0; mt < 4; mt++) {
                const uint32_t ab = cur + a_ldm[mt] + ks * 32;
                ldsm_x4(ah[mt][0], ah[mt][1], ah[mt][2], ah[mt][3], ab);
                ldsm_x4(al[mt][0], al[mt][1], al[mt][2], al[mt][3], ab + OFF_ALO);
            }
#pragma unroll
            for (int p = 0; p < 4; p++) {
                const uint32_t bb = cur + b_ldm[p] + ks * 32;
                uint32_t bh[4], bl[4];
                ldsm_x4(bh[0], bh[1], bh[2], bh[3], bb);
                ldsm_x4(bl[0], bl[1], bl[2], bl[3], bb + (OFF_BLO - OFF_BHI));
#pragma unroll
                for (int mt = 0; mt < 4; mt++) {
                    mma_bf16(acc[mt][2 * p + 0], ah[mt], &bh[0]);
                    mma_bf16(acc[mt][2 * p + 0], ah[mt], &bl[0]);
                    mma_bf16(acc[mt][2 * p + 0], al[mt], &bh[0]);
                    mma_bf16(acc[mt][2 * p + 1], ah[mt], &bh[2]);
                    mma_bf16(acc[mt][2 * p + 1], ah[mt], &bl[2]);
                    mma_bf16(acc[mt][2 * p + 1], al[mt], &bh[2]);
                }
            }
        }
        if (kc + 1 < NC) {
            const uint32_t nxt = sb + (uint32_t)((kc + 1) & 1) * STAGE;
            uint32_t h[8], l[8];
#pragma unroll
            for (int i = 0; i < 4; i++) {
                split_pair(av[i].x, av[i].y, h[2 * i + 0], l[2 * i + 0]);
                split_pair(av[i].z, av[i].w, h[2 * i + 1], l[2 * i + 1]);
            }
            sts_v4(nxt + a_sts, h[0], h[1], h[2], h[3]);
            sts_v4(nxt + a_sts + 16, h[4], h[5], h[6], h[7]);
            sts_v4(nxt + OFF_ALO + a_sts, l[0], l[1], l[2], l[3]);
            sts_v4(nxt + OFF_ALO + a_sts + 16, l[4], l[5], l[6], l[7]);
#pragma unroll
            for (int j = 0; j < 4; j++) {
                uint32_t bh[4], bl[4];
                split_pair(bv[0][j], bv[1][j], bh[0], bl[0]);
                split_pair(bv[2][j], bv[3][j], bh[1], bl[1]);
                split_pair(bv[4][j], bv[5][j], bh[2], bl[2]);
                split_pair(bv[6][j], bv[7][j], bh[3], bl[3]);
                sts_v4(nxt + OFF_BHI + b_sts0 + j * 5120, bh[0], bh[1], bh[2], bh[3]);
                sts_v4(nxt + OFF_BLO + b_sts0 + j * 5120, bl[0], bl[1], bl[2], bl[3]);
            }
        }
        __syncthreads();
    }

    // ---- epilogue ----
    const float* bs = biasw + (size_t)e * NTOT;
    const int trow = qid, tcol = tig * 2;
    float2 bb2[8];
#pragma unroll
    for (int nt = 0; nt < 8; nt++) {
        int col = n0 + wn * 64 + nt * 8 + tcol;
        bb2[nt] = *(const float2*)(bs + col);
    }
#pragma unroll
    for (int mt = 0; mt < 4; mt++) {
        int r0 = m0 + wm * 64 + mt * 16 + trow;
        int r1 = r0 + 8;
        bool v0 = r0 < end, v1 = r1 < end;
        int c0 = SCATTER ? (v0 ? g_perm[r0] : 0) : r0;
        int c1 = SCATTER ? (v1 ? g_perm[r1] : 0) : r1;
        float* p0 = C + (size_t)c0 * NTOT + n0 + wn * 64 + tcol;
        float* p1 = C + (size_t)c1 * NTOT + n0 + wn * 64 + tcol;
#pragma unroll
        for (int nt = 0; nt < 8; nt++) {
            float2 o0, o1;
            o0.x = acc[mt][nt][0] + bb2[nt].x;
            o0.y = acc[mt][nt][1] + bb2[nt].y;
            o1.x = acc[mt][nt][2] + bb2[nt].x;
            o1.y = acc[mt][nt][3] + bb2[nt].y;
            if (RELU) {
                o0.x = fmaxf(o0.x, 0.f); o0.y = fmaxf(o0.y, 0.f);
                o1.x = fmaxf(o1.x, 0.f); o1.y = fmaxf(o1.y, 0.f);
            }
            if (v0) *(float2*)(p0 + nt * 8) = o0;
            if (v1) *(float2*)(p1 + nt * 8) = o1;
        }
    }
}

// ---------------- router argmax + gap-based suspect detection ----------------
__global__ void init_counts()
{
    if (threadIdx.x < NE) g_counts[threadIdx.x] = 0;
    if (threadIdx.x == 0) g_nsus = 0;
}

__global__ __launch_bounds__(256)
void router_argmax(const float* __restrict__ Wr2, const float* __restrict__ br2)
{
    int gid = blockIdx.x * blockDim.x + threadIdx.x;
    int t = gid >> 5;
    int lane = gid & 31;
    if (t >= N_TOK) return;
    const float* h = g_H + (size_t)t * EMB;
    float acc[NE];
#pragma unroll
    for (int e = 0; e < NE; e++) acc[e] = 0.f;
    for (int i = lane; i < EMB; i += 32) {
        float hv = h[i];
        const float4 w0 = *(const float4*)(Wr2 + (size_t)i * NE);
        const float4 w1 = *(const float4*)(Wr2 + (size_t)i * NE + 4);
        acc[0] = fmaf(hv, w0.x, acc[0]);
        acc[1] = fmaf(hv, w0.y, acc[1]);
        acc[2] = fmaf(hv, w0.z, acc[2]);
        acc[3] = fmaf(hv, w0.w, acc[3]);
        acc[4] = fmaf(hv, w1.x, acc[4]);
        acc[5] = fmaf(hv, w1.y, acc[5]);
        acc[6] = fmaf(hv, w1.z, acc[6]);
        acc[7] = fmaf(hv, w1.w, acc[7]);
    }
#pragma unroll
    for (int off = 16; off > 0; off >>= 1)
#pragma unroll
        for (int e = 0; e < NE; e++)
            acc[e] += __shfl_xor_sync(0xffffffffu, acc[e], off);
    if (lane == 0) {
        int best = 0;
        float bv = acc[0] + br2[0], sv = -3.4e38f;
#pragma unroll
        for (int e = 1; e < NE; e++) {
            float v = acc[e] + br2[e];
            if (v > bv) { sv = bv; bv = v; best = e; }
            else if (v > sv) sv = v;
        }
        g_chosen[t] = best;
        if (bv - sv < GAP_THR) {
            int pos = atomicAdd(&g_nsus, 1);
            g_suspects[pos] = t;
        }
    }
}

// exact fp32 recompute of borderline tokens (one CTA per suspect, deterministic)
__global__ __launch_bounds__(256)
void router_fixup(const float* __restrict__ x, const float* __restrict__ Wr1,
                  const float* __restrict__ br1, const float* __restrict__ Wr2,
                  const float* __restrict__ br2)
{
    __shared__ float xs[EMB];
    __shared__ float hs[EMB];
    __shared__ float red[8][NE];
    const int tid = threadIdx.x, wid = tid >> 5, lane = tid & 31;
    const int ns = g_nsus;
    for (int si = blockIdx.x; si < ns; si += gridDim.x) {
        const int t = g_suspects[si];
        for (int i = tid; i < EMB; i += 256) xs[i] = x[(size_t)t * EMB + i];
        __syncthreads();
        float a0 = 0.f, a1 = 0.f, a2 = 0.f, a3 = 0.f;
        for (int k = 0; k < EMB; k++) {
            float xv = xs[k];
            const float* wr = Wr1 + (size_t)k * EMB + tid;
            a0 = fmaf(xv, wr[0], a0);
            a1 = fmaf(xv, wr[256], a1);
            a2 = fmaf(xv, wr[512], a2);
            a3 = fmaf(xv, wr[768], a3);
        }
        hs[tid + 0]   = fmaxf(a0 + br1[tid + 0], 0.f);
        hs[tid + 256] = fmaxf(a1 + br1[tid + 256], 0.f);
        hs[tid + 512] = fmaxf(a2 + br1[tid + 512], 0.f);
        hs[tid + 768] = fmaxf(a3 + br1[tid + 768], 0.f);
        __syncthreads();
        float l[NE];
#pragma unroll
        for (int e = 0; e < NE; e++) l[e] = 0.f;
        for (int j = tid; j < EMB; j += 256) {
            float hv = hs[j];
            const float4 w0 = *(const float4*)(Wr2 + (size_t)j * NE);
            const float4 w1 = *(const float4*)(Wr2 + (size_t)j * NE + 4);
            l[0] = fmaf(hv, w0.x, l[0]); l[1] = fmaf(hv, w0.y, l[1]);
            l[2] = fmaf(hv, w0.z, l[2]); l[3] = fmaf(hv, w0.w, l[3]);
            l[4] = fmaf(hv, w1.x, l[4]); l[5] = fmaf(hv, w1.y, l[5]);
            l[6] = fmaf(hv, w1.z, l[6]); l[7] = fmaf(hv, w1.w, l[7]);
        }
#pragma unroll
        for (int off = 16; off > 0; off >>= 1)
#pragma unroll
            for (int e = 0; e < NE; e++) l[e] += __shfl_xor_sync(0xffffffffu, l[e], off);
        if (lane == 0)
#pragma unroll
            for (int e = 0; e < NE; e++) red[wid][e] = l[e];
        __syncthreads();
        if (tid == 0) {
            float lg[NE];
#pragma unroll
            for (int e = 0; e < NE; e++) {
                lg[e] = br2[e];
#pragma unroll
                for (int w = 0; w < 8; w++) lg[e] += red[w][e];
            }
            int best = 0;
            float bv = lg[0];
#pragma unroll
            for (int e = 1; e < NE; e++)
                if (lg[e] > bv) { bv = lg[e]; best = e; }
            g_chosen[t] = best;
        }
        __syncthreads();
    }
}

__global__ void count_tokens()
{
    int t = blockIdx.x * blockDim.x + threadIdx.x;
    if (t < N_TOK) atomicAdd(&g_counts[g_chosen[t]], 1);
}

__global__ void scan_offsets()
{
    if (threadIdx.x == 0 && blockIdx.x == 0) {
        int o = 0;
        for (int e = 0; e < NE; e++) {
            g_offsets[e] = o;
            g_cursor[e] = o;
            o += g_counts[e];
        }
        g_offsets[NE] = o;
    }
}

__global__ void scatter_tokens()
{
    int t = blockIdx.x * blockDim.x + threadIdx.x;
    if (t >= N_TOK) return;
    int e = g_chosen[t];
    int pos = atomicAdd(&g_cursor[e], 1);
    g_perm[pos] = t;
}

// ---------------- launch ----------------
extern "C" void kernel_launch(void* const* d_in, const int* in_sizes, int n_in,
                              void* d_out, int out_size)
{
    const float* x   = (const float*)d_in[0];
    const float* Wr1 = (const float*)d_in[1];
    const float* br1 = (const float*)d_in[2];
    const float* Wr2 = (const float*)d_in[3];
    const float* br2 = (const float*)d_in[4];
    const float* W1  = (const float*)d_in[5];
    const float* b1  = (const float*)d_in[6];
    const float* W2  = (const float*)d_in[7];
    const float* b2  = (const float*)d_in[8];
    float* out = (float*)d_out;

    auto* kRouter = ffn_mma<EMB, EMB, false, false, true, false, 0, 2>;
    auto* kFfn1   = ffn_mma<HID, EMB, true, true, true, false, 0, 1>;
    auto* kFfn2   = ffn_mma<EMB, HID, true, false, false, true, 1, 0>;
    cudaFuncSetAttribute(kRouter, cudaFuncAttributeMaxDynamicSharedMemorySize, FFN_SMEM);
    cudaFuncSetAttribute(kFfn1, cudaFuncAttributeMaxDynamicSharedMemorySize, FFN_SMEM);
    cudaFuncSetAttribute(kFfn2, cudaFuncAttributeMaxDynamicSharedMemorySize, FFN_SMEM);

    init_counts<<<1, 32>>>();
    kRouter<<<dim3(N_TOK / 128, EMB / 256, 1), 256, FFN_SMEM>>>(x, Wr1, br1, nullptr);
    router_argmax<<<(N_TOK * 32) / 256, 256>>>(Wr2, br2);
    router_fixup<<<128, 256>>>(x, Wr1, br1, Wr2, br2);
    count_tokens<<<N_TOK / 256, 256>>>();
    scan_offsets<<<1, 1>>>();
    scatter_tokens<<<N_TOK / 256, 256>>>();
    kFfn1<<<dim3(N_TOK / 128, HID / 256, NE), 256, FFN_SMEM>>>(x, W1, b1, nullptr);
    kFfn2<<<dim3(N_TOK / 128, EMB / 256, NE), 256, FFN_SMEM>>>(nullptr, W2, b2, out);
}

// round 16
// speedup vs baseline: 1.6599x; 1.0544x over previous
#include <cuda_runtime.h>
#include <cstdint>

#define N_TOK 8192
#define EMB 1024
#define HID 4096
#define NE 8
#define GAP_THR 4e-4f

// ---------------- device scratch (no allocations allowed) ----------------
// NEVER pass these as kernel arguments from host code (ATS host-shadow bug).
__device__ float g_H[(size_t)N_TOK * EMB];        // router hidden (bf16x3 approx)
__device__ float g_hidden[(size_t)N_TOK * HID];   // expert hidden (permuted rows)
__device__ float g_plog[(size_t)N_TOK * 8 * NE];  // per-suspect per-chunk partial logits
__device__ int   g_chosen[N_TOK];
__device__ int   g_counts[NE];
__device__ int   g_offsets[NE + 1];
__device__ int   g_cursor[NE];
__device__ int   g_perm[N_TOK];
__device__ int   g_suspects[N_TOK];
__device__ int   g_nsus;

// ---------------- helpers ----------------
__device__ __forceinline__ uint32_t smem_u32(const void* p) {
    uint32_t a;
    asm("{ .reg .u64 t; cvta.to.shared.u64 t, %1; cvt.u32.u64 %0, t; }" : "=r"(a) : "l"(p));
    return a;
}
__device__ __forceinline__ void ldsm_x4(uint32_t& r0, uint32_t& r1, uint32_t& r2, uint32_t& r3,
                                        uint32_t addr) {
    asm volatile("ldmatrix.sync.aligned.m8n8.x4.shared.b16 {%0,%1,%2,%3}, [%4];"
                 : "=r"(r0), "=r"(r1), "=r"(r2), "=r"(r3) : "r"(addr));
}
__device__ __forceinline__ void mma_bf16(float* c, const uint32_t* a, const uint32_t* b) {
    asm volatile(
        "mma.sync.aligned.m16n8k16.row.col.f32.bf16.bf16.f32 "
        "{%0,%1,%2,%3}, {%4,%5,%6,%7}, {%8,%9}, {%0,%1,%2,%3};"
        : "+f"(c[0]), "+f"(c[1]), "+f"(c[2]), "+f"(c[3])
        : "r"(a[0]), "r"(a[1]), "r"(a[2]), "r"(a[3]), "r"(b[0]), "r"(b[1]));
}
__device__ __forceinline__ uint32_t bf16x2(float x, float y) {  // x->low, y->high
    uint32_t r;
    asm("cvt.rn.bf16x2.f32 %0, %1, %2;" : "=r"(r) : "f"(y), "f"(x));
    return r;
}
__device__ __forceinline__ void split_pair(float x, float y, uint32_t& hi, uint32_t& lo) {
    hi = bf16x2(x, y);
    float hx = __uint_as_float(hi << 16);
    float hy = __uint_as_float(hi & 0xFFFF0000u);
    lo = bf16x2(x - hx, y - hy);
}
__device__ __forceinline__ void sts_v4(uint32_t addr, uint32_t a, uint32_t b, uint32_t c, uint32_t d) {
    asm volatile("st.shared.v4.b32 [%0], {%1,%2,%3,%4};" :: "r"(addr), "r"(a), "r"(b), "r"(c), "r"(d) : "memory");
}

// SMEM stage layout (bf16, row stride 40 elems = 80 B, conflict-free):
// A_hi [0,10240) | A_lo [10240,20480) | B_hi [20480,40960) | B_lo [40960,61440)
#define RS 40
#define OFF_ALO 10240u
#define OFF_BHI 20480u
#define OFF_BLO 40960u
#define STAGE 61440u
#define FFN_SMEM (2 * 61440)

// ============================================================================
// bf16x3 mma.sync GEMM (verified R12/R13/R15). CTA tile 128x256, BK=32, 8 warps 64x64.
// SRC: 0=Ain param, 1=g_hidden. DST: 0=Cout param, 1=g_hidden, 2=g_H.
// ============================================================================
template <int NTOT, int KTOT, bool EXPERT, bool GATHER, bool RELU, bool SCATTER,
          int SRC, int DST>
__global__ __launch_bounds__(256, 1) void ffn_mma(
    const float* __restrict__ Ain, const float* __restrict__ Bw,
    const float* __restrict__ biasw, float* __restrict__ Cout)
{
    extern __shared__ __align__(16) uint8_t smem[];
    const float* A = (SRC == 1) ? (const float*)g_hidden : Ain;
    float* C = (DST == 1) ? (float*)g_hidden : ((DST == 2) ? (float*)g_H : Cout);

    int e = 0, start = 0, end = N_TOK;
    if (EXPERT) { e = blockIdx.z; start = g_offsets[e]; end = g_offsets[e + 1]; }
    const int m0 = start + blockIdx.x * 128;
    if (m0 >= end) return;
    const int n0 = blockIdx.y * 256;
    const float* Bm = Bw + (size_t)e * KTOT * NTOT;
    const uint32_t sb = smem_u32(smem);

    const int tid = threadIdx.x, wid = tid >> 5, lane = tid & 31;
    const int wm = wid & 1, wn = wid >> 1, qid = lane >> 2, tig = lane & 3;

    // A loader
    const int ar = tid >> 1;
    const int akc = (tid & 1) * 16;
    int rld = m0 + ar;
    int rc = (rld < end) ? rld : start;
    int grow = GATHER ? g_perm[rc] : rc;
    const float* Ap = A + (size_t)grow * KTOT + akc;
    const uint32_t a_sts = (uint32_t)(ar * RS + akc) * 2;

    // B loader: k-group = (tid>>6)*8, n = (tid&63) + 64j
    const int bk = (tid >> 6) * 8;
    const int bn = tid & 63;
    const float* Bp = Bm + n0 + bn;
    const uint32_t b_sts0 = (uint32_t)(bn * RS + bk) * 2;

    uint32_t a_ldm[4];
#pragma unroll
    for (int mt = 0; mt < 4; mt++)
        a_ldm[mt] = (uint32_t)((wm * 64 + mt * 16 + (lane & 15)) * RS) * 2 +
                    ((lane >> 4) & 1) * 16;
    uint32_t b_ldm[4];
#pragma unroll
    for (int p = 0; p < 4; p++)
        b_ldm[p] = OFF_BHI +
                   (uint32_t)((wn * 64 + p * 16 + (lane & 7) + ((lane >> 4) & 1) * 8) * RS) * 2 +
                   ((lane >> 3) & 1) * 16;

    float acc[4][8][4];
#pragma unroll
    for (int mt = 0; mt < 4; mt++)
#pragma unroll
        for (int nt = 0; nt < 8; nt++)
#pragma unroll
            for (int i = 0; i < 4; i++) acc[mt][nt][i] = 0.f;

    float4 av[4];
    float bv[8][4];
    const int NC = KTOT / 32;

#pragma unroll
    for (int i = 0; i < 4; i++) av[i] = *(const float4*)(Ap + 4 * i);
#pragma unroll
    for (int i = 0; i < 8; i++) {
        const float* rowp = Bp + (size_t)(bk + i) * NTOT;
#pragma unroll
        for (int j = 0; j < 4; j++) bv[i][j] = rowp[64 * j];
    }
    {
        uint32_t h[8], l[8];
#pragma unroll
        for (int i = 0; i < 4; i++) {
            split_pair(av[i].x, av[i].y, h[2 * i + 0], l[2 * i + 0]);
            split_pair(av[i].z, av[i].w, h[2 * i + 1], l[2 * i + 1]);
        }
        sts_v4(sb + a_sts, h[0], h[1], h[2], h[3]);
        sts_v4(sb + a_sts + 16, h[4], h[5], h[6], h[7]);
        sts_v4(sb + OFF_ALO + a_sts, l[0], l[1], l[2], l[3]);
        sts_v4(sb + OFF_ALO + a_sts + 16, l[4], l[5], l[6], l[7]);
#pragma unroll
        for (int j = 0; j < 4; j++) {
            uint32_t bh[4], bl[4];
            split_pair(bv[0][j], bv[1][j], bh[0], bl[0]);
            split_pair(bv[2][j], bv[3][j], bh[1], bl[1]);
            split_pair(bv[4][j], bv[5][j], bh[2], bl[2]);
            split_pair(bv[6][j], bv[7][j], bh[3], bl[3]);
            sts_v4(sb + OFF_BHI + b_sts0 + j * 5120, bh[0], bh[1], bh[2], bh[3]);
            sts_v4(sb + OFF_BLO + b_sts0 + j * 5120, bl[0], bl[1], bl[2], bl[3]);
        }
    }
    __syncthreads();

#pragma unroll 1
    for (int kc = 0; kc < NC; kc++) {
        if (kc + 1 < NC) {
            const int k0 = (kc + 1) * 32;
#pragma unroll
            for (int i = 0; i < 4; i++) av[i] = *(const float4*)(Ap + k0 + 4 * i);
#pragma unroll
            for (int i = 0; i < 8; i++) {
                const float* rowp = Bp + (size_t)(k0 + bk + i) * NTOT;
#pragma unroll
                for (int j = 0; j < 4; j++) bv[i][j] = rowp[64 * j];
            }
        }
        const uint32_t cur = sb + (uint32_t)(kc & 1) * STAGE;
#pragma unroll
        for (int ks = 0; ks < 2; ks++) {
            uint32_t ah[4][4], al[4][4];
#pragma unroll
            for (int mt = 0; mt < 4; mt++) {
                const uint32_t ab = cur + a_ldm[mt] + ks * 32;
                ldsm_x4(ah[mt][0], ah[mt][1], ah[mt][2], ah[mt][3], ab);
                ldsm_x4(al[mt][0], al[mt][1], al[mt][2], al[mt][3], ab + OFF_ALO);
            }
#pragma unroll
            for (int p = 0; p < 4; p++) {
                const uint32_t bb = cur + b_ldm[p] + ks * 32;
                uint32_t bh[4], bl[4];
                ldsm_x4(bh[0], bh[1], bh[2], bh[3], bb);
                ldsm_x4(bl[0], bl[1], bl[2], bl[3], bb + (OFF_BLO - OFF_BHI));
#pragma unroll
                for (int mt = 0; mt < 4; mt++) {
                    mma_bf16(acc[mt][2 * p + 0], ah[mt], &bh[0]);
                    mma_bf16(acc[mt][2 * p + 0], ah[mt], &bl[0]);
                    mma_bf16(acc[mt][2 * p + 0], al[mt], &bh[0]);
                    mma_bf16(acc[mt][2 * p + 1], ah[mt], &bh[2]);
                    mma_bf16(acc[mt][2 * p + 1], ah[mt], &bl[2]);
                    mma_bf16(acc[mt][2 * p + 1], al[mt], &bh[2]);
                }
            }
        }
        if (kc + 1 < NC) {
            const uint32_t nxt = sb + (uint32_t)((kc + 1) & 1) * STAGE;
            uint32_t h[8], l[8];
#pragma unroll
            for (int i = 0; i < 4; i++) {
                split_pair(av[i].x, av[i].y, h[2 * i + 0], l[2 * i + 0]);
                split_pair(av[i].z, av[i].w, h[2 * i + 1], l[2 * i + 1]);
            }
            sts_v4(nxt + a_sts, h[0], h[1], h[2], h[3]);
            sts_v4(nxt + a_sts + 16, h[4], h[5], h[6], h[7]);
            sts_v4(nxt + OFF_ALO + a_sts, l[0], l[1], l[2], l[3]);
            sts_v4(nxt + OFF_ALO + a_sts + 16, l[4], l[5], l[6], l[7]);
#pragma unroll
            for (int j = 0; j < 4; j++) {
                uint32_t bh[4], bl[4];
                split_pair(bv[0][j], bv[1][j], bh[0], bl[0]);
                split_pair(bv[2][j], bv[3][j], bh[1], bl[1]);
                split_pair(bv[4][j], bv[5][j], bh[2], bl[2]);
                split_pair(bv[6][j], bv[7][j], bh[3], bl[3]);
                sts_v4(nxt + OFF_BHI + b_sts0 + j * 5120, bh[0], bh[1], bh[2], bh[3]);
                sts_v4(nxt + OFF_BLO + b_sts0 + j * 5120, bl[0], bl[1], bl[2], bl[3]);
            }
        }
        __syncthreads();
    }

    // ---- epilogue ----
    const float* bs = biasw + (size_t)e * NTOT;
    const int trow = qid, tcol = tig * 2;
    float2 bb2[8];
#pragma unroll
    for (int nt = 0; nt < 8; nt++) {
        int col = n0 + wn * 64 + nt * 8 + tcol;
        bb2[nt] = *(const float2*)(bs + col);
    }
#pragma unroll
    for (int mt = 0; mt < 4; mt++) {
        int r0 = m0 + wm * 64 + mt * 16 + trow;
        int r1 = r0 + 8;
        bool v0 = r0 < end, v1 = r1 < end;
        int c0 = SCATTER ? (v0 ? g_perm[r0] : 0) : r0;
        int c1 = SCATTER ? (v1 ? g_perm[r1] : 0) : r1;
        float* p0 = C + (size_t)c0 * NTOT + n0 + wn * 64 + tcol;
        float* p1 = C + (size_t)c1 * NTOT + n0 + wn * 64 + tcol;
#pragma unroll
        for (int nt = 0; nt < 8; nt++) {
            float2 o0, o1;
            o0.x = acc[mt][nt][0] + bb2[nt].x;
            o0.y = acc[mt][nt][1] + bb2[nt].y;
            o1.x = acc[mt][nt][2] + bb2[nt].x;
            o1.y = acc[mt][nt][3] + bb2[nt].y;
            if (RELU) {
                o0.x = fmaxf(o0.x, 0.f); o0.y = fmaxf(o0.y, 0.f);
                o1.x = fmaxf(o1.x, 0.f); o1.y = fmaxf(o1.y, 0.f);
            }
            if (v0) *(float2*)(p0 + nt * 8) = o0;
            if (v1) *(float2*)(p1 + nt * 8) = o1;
        }
    }
}

// ---------------- router argmax + gap-based suspect detection ----------------
__global__ void init_counts()
{
    if (threadIdx.x < NE) g_counts[threadIdx.x] = 0;
    if (threadIdx.x == 0) g_nsus = 0;
}

__global__ __launch_bounds__(256)
void router_argmax(const float* __restrict__ Wr2, const float* __restrict__ br2)
{
    int gid = blockIdx.x * blockDim.x + threadIdx.x;
    int t = gid >> 5;
    int lane = gid & 31;
    if (t >= N_TOK) return;
    const float* h = g_H + (size_t)t * EMB;
    float acc[NE];
#pragma unroll
    for (int e = 0; e < NE; e++) acc[e] = 0.f;
    for (int i = lane; i < EMB; i += 32) {
        float hv = h[i];
        const float4 w0 = *(const float4*)(Wr2 + (size_t)i * NE);
        const float4 w1 = *(const float4*)(Wr2 + (size_t)i * NE + 4);
        acc[0] = fmaf(hv, w0.x, acc[0]);
        acc[1] = fmaf(hv, w0.y, acc[1]);
        acc[2] = fmaf(hv, w0.z, acc[2]);
        acc[3] = fmaf(hv, w0.w, acc[3]);
        acc[4] = fmaf(hv, w1.x, acc[4]);
        acc[5] = fmaf(hv, w1.y, acc[5]);
        acc[6] = fmaf(hv, w1.z, acc[6]);
        acc[7] = fmaf(hv, w1.w, acc[7]);
    }
#pragma unroll
    for (int off = 16; off > 0; off >>= 1)
#pragma unroll
        for (int e = 0; e < NE; e++)
            acc[e] += __shfl_xor_sync(0xffffffffu, acc[e], off);
    if (lane == 0) {
        int best = 0;
        float bv = acc[0] + br2[0], sv = -3.4e38f;
#pragma unroll
        for (int e = 1; e < NE; e++) {
            float v = acc[e] + br2[e];
            if (v > bv) { sv = bv; bv = v; best = e; }
            else if (v > sv) sv = v;
        }
        g_chosen[t] = best;
        if (bv - sv < GAP_THR) {
            int pos = atomicAdd(&g_nsus, 1);
            g_suspects[pos] = t;
        }
    }
}

// ---------------- N-split exact fixup ----------------
// Phase A: CTA (cx, si) computes exact fp32 hidden slice [cx*128, cx*128+128)
// for suspect si and reduces it against Wr2 into 8 partial logits.
__global__ __launch_bounds__(256)
void fixup_partial(const float* __restrict__ x, const float* __restrict__ Wr1,
                   const float* __restrict__ br1, const float* __restrict__ Wr2)
{
    __shared__ float xs[EMB];
    __shared__ float part[2][128];
    __shared__ float lred[4][NE];
    const int ns = g_nsus;
    const int n0 = blockIdx.x * 128;
    const int tid = threadIdx.x;
    const int nl = tid & 127, half = tid >> 7;
    for (int si = blockIdx.y; si < ns; si += gridDim.y) {
        const int t = g_suspects[si];
        for (int i = tid; i < EMB; i += 256) xs[i] = x[(size_t)t * EMB + i];
        __syncthreads();
        // partial over k-half (fixed split -> deterministic)
        float acc = 0.f;
        const float* wp = Wr1 + (size_t)(half * 512) * EMB + n0 + nl;
        const float* xp = xs + half * 512;
#pragma unroll 8
        for (int k = 0; k < 512; k++)
            acc = fmaf(xp[k], wp[(size_t)k * EMB], acc);
        part[half][nl] = acc;
        __syncthreads();
        if (tid < 128) {
            float h = fmaxf(part[0][tid] + part[1][tid] + br1[n0 + tid], 0.f);
            float l[NE];
            const float* w2 = Wr2 + (size_t)(n0 + tid) * NE;
#pragma unroll
            for (int e = 0; e < NE; e++) l[e] = h * w2[e];
#pragma unroll
            for (int off = 16; off > 0; off >>= 1)
#pragma unroll
                for (int e = 0; e < NE; e++) l[e] += __shfl_xor_sync(0xffffffffu, l[e], off);
            if ((tid & 31) == 0)
#pragma unroll
                for (int e = 0; e < NE; e++) lred[tid >> 5][e] = l[e];
        }
        __syncthreads();
        if (tid == 0) {
#pragma unroll
            for (int e = 0; e < NE; e++)
                g_plog[((size_t)si * 8 + blockIdx.x) * NE + e] =
                    (lred[0][e] + lred[1][e]) + (lred[2][e] + lred[3][e]);
        }
        __syncthreads();
    }
}

// Phase B: sum the 8 chunk-partials in fixed order, argmax, correct g_chosen.
__global__ __launch_bounds__(256)
void fixup_resolve(const float* __restrict__ br2)
{
    int si = blockIdx.x * blockDim.x + threadIdx.x;
    if (si >= g_nsus) return;
    float lg[NE];
#pragma unroll
    for (int e = 0; e < NE; e++) lg[e] = br2[e];
#pragma unroll
    for (int c = 0; c < 8; c++)
#pragma unroll
        for (int e = 0; e < NE; e++)
            lg[e] += g_plog[((size_t)si * 8 + c) * NE + e];
    int best = 0;
    float bv = lg[0];
#pragma unroll
    for (int e = 1; e < NE; e++)
        if (lg[e] > bv) { bv = lg[e]; best = e; }
    g_chosen[g_suspects[si]] = best;
}

__global__ void count_tokens()
{
    int t = blockIdx.x * blockDim.x + threadIdx.x;
    if (t < N_TOK) atomicAdd(&g_counts[g_chosen[t]], 1);
}

__global__ void scan_offsets()
{
    if (threadIdx.x == 0 && blockIdx.x == 0) {
        int o = 0;
        for (int e = 0; e < NE; e++) {
            g_offsets[e] = o;
            g_cursor[e] = o;
            o += g_counts[e];
        }
        g_offsets[NE] = o;
    }
}

__global__ void scatter_tokens()
{
    int t = blockIdx.x * blockDim.x + threadIdx.x;
    if (t >= N_TOK) return;
    int e = g_chosen[t];
    int pos = atomicAdd(&g_cursor[e], 1);
    g_perm[pos] = t;
}

// ---------------- launch ----------------
extern "C" void kernel_launch(void* const* d_in, const int* in_sizes, int n_in,
                              void* d_out, int out_size)
{
    const float* x   = (const float*)d_in[0];
    const float* Wr1 = (const float*)d_in[1];
    const float* br1 = (const float*)d_in[2];
    const float* Wr2 = (const float*)d_in[3];
    const float* br2 = (const float*)d_in[4];
    const float* W1  = (const float*)d_in[5];
    const float* b1  = (const float*)d_in[6];
    const float* W2  = (const float*)d_in[7];
    const float* b2  = (const float*)d_in[8];
    float* out = (float*)d_out;

    auto* kRouter = ffn_mma<EMB, EMB, false, false, true, false, 0, 2>;
    auto* kFfn1   = ffn_mma<HID, EMB, true, true, true, false, 0, 1>;
    auto* kFfn2   = ffn_mma<EMB, HID, true, false, false, true, 1, 0>;
    cudaFuncSetAttribute(kRouter, cudaFuncAttributeMaxDynamicSharedMemorySize, FFN_SMEM);
    cudaFuncSetAttribute(kFfn1, cudaFuncAttributeMaxDynamicSharedMemorySize, FFN_SMEM);
    cudaFuncSetAttribute(kFfn2, cudaFuncAttributeMaxDynamicSharedMemorySize, FFN_SMEM);

    init_counts<<<1, 32>>>();
    kRouter<<<dim3(N_TOK / 128, EMB / 256, 1), 256, FFN_SMEM>>>(x, Wr1, br1, nullptr);
    router_argmax<<<(N_TOK * 32) / 256, 256>>>(Wr2, br2);
    fixup_partial<<<dim3(8, 256), 256>>>(x, Wr1, br1, Wr2);
    fixup_resolve<<<N_TOK / 256, 256>>>(br2);
    count_tokens<<<N_TOK / 256, 256>>>();
    scan_offsets<<<1, 1>>>();
    scatter_tokens<<<N_TOK / 256, 256>>>();
    kFfn1<<<dim3(N_TOK / 128, HID / 256, NE), 256, FFN_SMEM>>>(x, W1, b1, nullptr);
    kFfn2<<<dim3(N_TOK / 128, EMB / 256, NE), 256, FFN_SMEM>>>(nullptr, W2, b2, out);
}

// round 17
// speedup vs baseline: 1.6754x; 1.0093x over previous
#include <cuda_runtime.h>
#include <cstdint>

#define N_TOK 8192
#define EMB 1024
#define HID 4096
#define NE 8
#define GAP_THR 4e-4f

// ---------------- device scratch (no allocations allowed) ----------------
// NEVER pass these as kernel arguments from host code (ATS host-shadow bug).
__device__ float g_H[(size_t)N_TOK * EMB];        // router hidden (bf16x3 approx)
__device__ float g_hidden[(size_t)N_TOK * HID];   // expert hidden (permuted rows)
__device__ float g_plog[(size_t)N_TOK * 8 * NE];  // per-suspect per-chunk partial logits
__device__ int   g_chosen[N_TOK];
__device__ int   g_counts[NE];
__device__ int   g_offsets[NE + 1];
__device__ int   g_cursor[NE];
__device__ int   g_perm[N_TOK];
__device__ int   g_suspects[N_TOK];
__device__ int   g_nsus;

// ---------------- helpers ----------------
__device__ __forceinline__ uint32_t smem_u32(const void* p) {
    uint32_t a;
    asm("{ .reg .u64 t; cvta.to.shared.u64 t, %1; cvt.u32.u64 %0, t; }" : "=r"(a) : "l"(p));
    return a;
}
__device__ __forceinline__ void ldsm_x4(uint32_t& r0, uint32_t& r1, uint32_t& r2, uint32_t& r3,
                                        uint32_t addr) {
    asm volatile("ldmatrix.sync.aligned.m8n8.x4.shared.b16 {%0,%1,%2,%3}, [%4];"
                 : "=r"(r0), "=r"(r1), "=r"(r2), "=r"(r3) : "r"(addr));
}
__device__ __forceinline__ void mma_bf16(float* c, const uint32_t* a, const uint32_t* b) {
    asm volatile(
        "mma.sync.aligned.m16n8k16.row.col.f32.bf16.bf16.f32 "
        "{%0,%1,%2,%3}, {%4,%5,%6,%7}, {%8,%9}, {%0,%1,%2,%3};"
        : "+f"(c[0]), "+f"(c[1]), "+f"(c[2]), "+f"(c[3])
        : "r"(a[0]), "r"(a[1]), "r"(a[2]), "r"(a[3]), "r"(b[0]), "r"(b[1]));
}
__device__ __forceinline__ uint32_t bf16x2(float x, float y) {  // x->low, y->high
    uint32_t r;
    asm("cvt.rn.bf16x2.f32 %0, %1, %2;" : "=r"(r) : "f"(y), "f"(x));
    return r;
}
__device__ __forceinline__ void split_pair(float x, float y, uint32_t& hi, uint32_t& lo) {
    hi = bf16x2(x, y);
    float hx = __uint_as_float(hi << 16);
    float hy = __uint_as_float(hi & 0xFFFF0000u);
    lo = bf16x2(x - hx, y - hy);
}
__device__ __forceinline__ void sts_v4(uint32_t addr, uint32_t a, uint32_t b, uint32_t c, uint32_t d) {
    asm volatile("st.shared.v4.b32 [%0], {%1,%2,%3,%4};" :: "r"(addr), "r"(a), "r"(b), "r"(c), "r"(d) : "memory");
}

// SMEM stage layout (bf16, row stride 40 elems = 80 B, conflict-free):
// A_hi [0,10240) | A_lo [10240,20480) | B_hi [20480,40960) | B_lo [40960,61440)
#define RS 40
#define OFF_ALO 10240u
#define OFF_BHI 20480u
#define OFF_BLO 40960u
#define STAGE 61440u
#define FFN_SMEM (2 * 61440)

// ============================================================================
// bf16x3 mma.sync GEMM (verified R12..R16). CTA tile 128x256, BK=32, 8 warps 64x64.
// Inner loop reordered term-major so same-accumulator MMAs are 8 apart.
// SRC: 0=Ain param, 1=g_hidden. DST: 0=Cout param, 1=g_hidden, 2=g_H.
// ============================================================================
template <int NTOT, int KTOT, bool EXPERT, bool GATHER, bool RELU, bool SCATTER,
          int SRC, int DST>
__global__ __launch_bounds__(256, 1) void ffn_mma(
    const float* __restrict__ Ain, const float* __restrict__ Bw,
    const float* __restrict__ biasw, float* __restrict__ Cout)
{
    extern __shared__ __align__(16) uint8_t smem[];
    const float* A = (SRC == 1) ? (const float*)g_hidden : Ain;
    float* C = (DST == 1) ? (float*)g_hidden : ((DST == 2) ? (float*)g_H : Cout);

    int e = 0, start = 0, end = N_TOK;
    if (EXPERT) { e = blockIdx.z; start = g_offsets[e]; end = g_offsets[e + 1]; }
    const int m0 = start + blockIdx.x * 128;
    if (m0 >= end) return;
    const int n0 = blockIdx.y * 256;
    const float* Bm = Bw + (size_t)e * KTOT * NTOT;
    const uint32_t sb = smem_u32(smem);

    const int tid = threadIdx.x, wid = tid >> 5, lane = tid & 31;
    const int wm = wid & 1, wn = wid >> 1, qid = lane >> 2, tig = lane & 3;

    // A loader
    const int ar = tid >> 1;
    const int akc = (tid & 1) * 16;
    int rld = m0 + ar;
    int rc = (rld < end) ? rld : start;
    int grow = GATHER ? g_perm[rc] : rc;
    const float* Ap = A + (size_t)grow * KTOT + akc;
    const uint32_t a_sts = (uint32_t)(ar * RS + akc) * 2;

    // B loader: k-group = (tid>>6)*8, n = (tid&63) + 64j
    const int bk = (tid >> 6) * 8;
    const int bn = tid & 63;
    const float* Bp = Bm + n0 + bn;
    const uint32_t b_sts0 = (uint32_t)(bn * RS + bk) * 2;

    uint32_t a_ldm[4];
#pragma unroll
    for (int mt = 0; mt < 4; mt++)
        a_ldm[mt] = (uint32_t)((wm * 64 + mt * 16 + (lane & 15)) * RS) * 2 +
                    ((lane >> 4) & 1) * 16;
    uint32_t b_ldm[4];
#pragma unroll
    for (int p = 0; p < 4; p++)
        b_ldm[p] = OFF_BHI +
                   (uint32_t)((wn * 64 + p * 16 + (lane & 7) + ((lane >> 4) & 1) * 8) * RS) * 2 +
                   ((lane >> 3) & 1) * 16;

    float acc[4][8][4];
#pragma unroll
    for (int mt = 0; mt < 4; mt++)
#pragma unroll
        for (int nt = 0; nt < 8; nt++)
#pragma unroll
            for (int i = 0; i < 4; i++) acc[mt][nt][i] = 0.f;

    float4 av[4];
    float bv[8][4];
    const int NC = KTOT / 32;

#pragma unroll
    for (int i = 0; i < 4; i++) av[i] = *(const float4*)(Ap + 4 * i);
#pragma unroll
    for (int i = 0; i < 8; i++) {
        const float* rowp = Bp + (size_t)(bk + i) * NTOT;
#pragma unroll
        for (int j = 0; j < 4; j++) bv[i][j] = rowp[64 * j];
    }
    {
        uint32_t h[8], l[8];
#pragma unroll
        for (int i = 0; i < 4; i++) {
            split_pair(av[i].x, av[i].y, h[2 * i + 0], l[2 * i + 0]);
            split_pair(av[i].z, av[i].w, h[2 * i + 1], l[2 * i + 1]);
        }
        sts_v4(sb + a_sts, h[0], h[1], h[2], h[3]);
        sts_v4(sb + a_sts + 16, h[4], h[5], h[6], h[7]);
        sts_v4(sb + OFF_ALO + a_sts, l[0], l[1], l[2], l[3]);
        sts_v4(sb + OFF_ALO + a_sts + 16, l[4], l[5], l[6], l[7]);
#pragma unroll
        for (int j = 0; j < 4; j++) {
            uint32_t bh[4], bl[4];
            split_pair(bv[0][j], bv[1][j], bh[0], bl[0]);
            split_pair(bv[2][j], bv[3][j], bh[1], bl[1]);
            split_pair(bv[4][j], bv[5][j], bh[2], bl[2]);
            split_pair(bv[6][j], bv[7][j], bh[3], bl[3]);
            sts_v4(sb + OFF_BHI + b_sts0 + j * 5120, bh[0], bh[1], bh[2], bh[3]);
            sts_v4(sb + OFF_BLO + b_sts0 + j * 5120, bl[0], bl[1], bl[2], bl[3]);
        }
    }
    __syncthreads();

#pragma unroll 1
    for (int kc = 0; kc < NC; kc++) {
        if (kc + 1 < NC) {
            const int k0 = (kc + 1) * 32;
#pragma unroll
            for (int i = 0; i < 4; i++) av[i] = *(const float4*)(Ap + k0 + 4 * i);
#pragma unroll
            for (int i = 0; i < 8; i++) {
                const float* rowp = Bp + (size_t)(k0 + bk + i) * NTOT;
#pragma unroll
                for (int j = 0; j < 4; j++) bv[i][j] = rowp[64 * j];
            }
        }
        const uint32_t cur = sb + (uint32_t)(kc & 1) * STAGE;
#pragma unroll
        for (int ks = 0; ks < 2; ks++) {
            uint32_t ah[4][4], al[4][4];
#pragma unroll
            for (int mt = 0; mt < 4; mt++) {
                const uint32_t ab = cur + a_ldm[mt] + ks * 32;
                ldsm_x4(ah[mt][0], ah[mt][1], ah[mt][2], ah[mt][3], ab);
                ldsm_x4(al[mt][0], al[mt][1], al[mt][2], al[mt][3], ab + OFF_ALO);
            }
#pragma unroll
            for (int p = 0; p < 4; p++) {
                const uint32_t bb = cur + b_ldm[p] + ks * 32;
                uint32_t bh[4], bl[4];
                ldsm_x4(bh[0], bh[1], bh[2], bh[3], bb);
                ldsm_x4(bl[0], bl[1], bl[2], bl[3], bb + (OFF_BLO - OFF_BHI));
                // term-major: same-acc MMAs spaced 8 apart; per-acc fp32 order
                // stays hh -> hl -> lh (identical numerics to R12-R16).
#pragma unroll
                for (int q = 0; q < 2; q++)
#pragma unroll
                    for (int mt = 0; mt < 4; mt++)
                        mma_bf16(acc[mt][2 * p + q], ah[mt], &bh[2 * q]);
#pragma unroll
                for (int q = 0; q < 2; q++)
#pragma unroll
                    for (int mt = 0; mt < 4; mt++)
                        mma_bf16(acc[mt][2 * p + q], ah[mt], &bl[2 * q]);
#pragma unroll
                for (int q = 0; q < 2; q++)
#pragma unroll
                    for (int mt = 0; mt < 4; mt++)
                        mma_bf16(acc[mt][2 * p + q], al[mt], &bh[2 * q]);
            }
        }
        if (kc + 1 < NC) {
            const uint32_t nxt = sb + (uint32_t)((kc + 1) & 1) * STAGE;
            uint32_t h[8], l[8];
#pragma unroll
            for (int i = 0; i < 4; i++) {
                split_pair(av[i].x, av[i].y, h[2 * i + 0], l[2 * i + 0]);
                split_pair(av[i].z, av[i].w, h[2 * i + 1], l[2 * i + 1]);
            }
            sts_v4(nxt + a_sts, h[0], h[1], h[2], h[3]);
            sts_v4(nxt + a_sts + 16, h[4], h[5], h[6], h[7]);
            sts_v4(nxt + OFF_ALO + a_sts, l[0], l[1], l[2], l[3]);
            sts_v4(nxt + OFF_ALO + a_sts + 16, l[4], l[5], l[6], l[7]);
#pragma unroll
            for (int j = 0; j < 4; j++) {
                uint32_t bh[4], bl[4];
                split_pair(bv[0][j], bv[1][j], bh[0], bl[0]);
                split_pair(bv[2][j], bv[3][j], bh[1], bl[1]);
                split_pair(bv[4][j], bv[5][j], bh[2], bl[2]);
                split_pair(bv[6][j], bv[7][j], bh[3], bl[3]);
                sts_v4(nxt + OFF_BHI + b_sts0 + j * 5120, bh[0], bh[1], bh[2], bh[3]);
                sts_v4(nxt + OFF_BLO + b_sts0 + j * 5120, bl[0], bl[1], bl[2], bl[3]);
            }
        }
        __syncthreads();
    }

    // ---- epilogue ----
    const float* bs = biasw + (size_t)e * NTOT;
    const int trow = qid, tcol = tig * 2;
    float2 bb2[8];
#pragma unroll
    for (int nt = 0; nt < 8; nt++) {
        int col = n0 + wn * 64 + nt * 8 + tcol;
        bb2[nt] = *(const float2*)(bs + col);
    }
#pragma unroll
    for (int mt = 0; mt < 4; mt++) {
        int r0 = m0 + wm * 64 + mt * 16 + trow;
        int r1 = r0 + 8;
        bool v0 = r0 < end, v1 = r1 < end;
        int c0 = SCATTER ? (v0 ? g_perm[r0] : 0) : r0;
        int c1 = SCATTER ? (v1 ? g_perm[r1] : 0) : r1;
        float* p0 = C + (size_t)c0 * NTOT + n0 + wn * 64 + tcol;
        float* p1 = C + (size_t)c1 * NTOT + n0 + wn * 64 + tcol;
#pragma unroll
        for (int nt = 0; nt < 8; nt++) {
            float2 o0, o1;
            o0.x = acc[mt][nt][0] + bb2[nt].x;
            o0.y = acc[mt][nt][1] + bb2[nt].y;
            o1.x = acc[mt][nt][2] + bb2[nt].x;
            o1.y = acc[mt][nt][3] + bb2[nt].y;
            if (RELU) {
                o0.x = fmaxf(o0.x, 0.f); o0.y = fmaxf(o0.y, 0.f);
                o1.x = fmaxf(o1.x, 0.f); o1.y = fmaxf(o1.y, 0.f);
            }
            if (v0) *(float2*)(p0 + nt * 8) = o0;
            if (v1) *(float2*)(p1 + nt * 8) = o1;
        }
    }
}

// ---------------- router argmax + gap-based suspect detection ----------------
__global__ void init_counts()
{
    if (threadIdx.x < NE) g_counts[threadIdx.x] = 0;
    if (threadIdx.x == 0) g_nsus = 0;
}

__global__ __launch_bounds__(256)
void router_argmax(const float* __restrict__ Wr2, const float* __restrict__ br2)
{
    int gid = blockIdx.x * blockDim.x + threadIdx.x;
    int t = gid >> 5;
    int lane = gid & 31;
    if (t >= N_TOK) return;
    const float* h = g_H + (size_t)t * EMB;
    float acc[NE];
#pragma unroll
    for (int e = 0; e < NE; e++) acc[e] = 0.f;
    for (int i = lane; i < EMB; i += 32) {
        float hv = h[i];
        const float4 w0 = *(const float4*)(Wr2 + (size_t)i * NE);
        const float4 w1 = *(const float4*)(Wr2 + (size_t)i * NE + 4);
        acc[0] = fmaf(hv, w0.x, acc[0]);
        acc[1] = fmaf(hv, w0.y, acc[1]);
        acc[2] = fmaf(hv, w0.z, acc[2]);
        acc[3] = fmaf(hv, w0.w, acc[3]);
        acc[4] = fmaf(hv, w1.x, acc[4]);
        acc[5] = fmaf(hv, w1.y, acc[5]);
        acc[6] = fmaf(hv, w1.z, acc[6]);
        acc[7] = fmaf(hv, w1.w, acc[7]);
    }
#pragma unroll
    for (int off = 16; off > 0; off >>= 1)
#pragma unroll
        for (int e = 0; e < NE; e++)
            acc[e] += __shfl_xor_sync(0xffffffffu, acc[e], off);
    if (lane == 0) {
        int best = 0;
        float bv = acc[0] + br2[0], sv = -3.4e38f;
#pragma unroll
        for (int e = 1; e < NE; e++) {
            float v = acc[e] + br2[e];
            if (v > bv) { sv = bv; bv = v; best = e; }
            else if (v > sv) sv = v;
        }
        g_chosen[t] = best;
        if (bv - sv < GAP_THR) {
            int pos = atomicAdd(&g_nsus, 1);
            g_suspects[pos] = t;
        }
    }
}

// ---------------- N-split exact fixup ----------------
// Phase A: CTA (cx, si) computes exact fp32 hidden slice [cx*128, cx*128+128)
// for suspect si and reduces it against Wr2 into 8 partial logits.
__global__ __launch_bounds__(256)
void fixup_partial(const float* __restrict__ x, const float* __restrict__ Wr1,
                   const float* __restrict__ br1, const float* __restrict__ Wr2)
{
    __shared__ float xs[EMB];
    __shared__ float part[2][128];
    __shared__ float lred[4][NE];
    const int ns = g_nsus;
    const int n0 = blockIdx.x * 128;
    const int tid = threadIdx.x;
    const int nl = tid & 127, half = tid >> 7;
    for (int si = blockIdx.y; si < ns; si += gridDim.y) {
        const int t = g_suspects[si];
        for (int i = tid; i < EMB; i += 256) xs[i] = x[(size_t)t * EMB + i];
        __syncthreads();
        // 4 interleaved accumulators -> 4x shorter FMA chain, deterministic combine
        float a0 = 0.f, a1 = 0.f, a2 = 0.f, a3 = 0.f;
        const float* wp = Wr1 + (size_t)(half * 512) * EMB + n0 + nl;
        const float* xp = xs + half * 512;
#pragma unroll 4
        for (int k = 0; k < 512; k += 4) {
            a0 = fmaf(xp[k + 0], wp[(size_t)(k + 0) * EMB], a0);
            a1 = fmaf(xp[k + 1], wp[(size_t)(k + 1) * EMB], a1);
            a2 = fmaf(xp[k + 2], wp[(size_t)(k + 2) * EMB], a2);
            a3 = fmaf(xp[k + 3], wp[(size_t)(k + 3) * EMB], a3);
        }
        part[half][nl] = (a0 + a1) + (a2 + a3);
        __syncthreads();
        if (tid < 128) {
            float h = fmaxf(part[0][tid] + part[1][tid] + br1[n0 + tid], 0.f);
            float l[NE];
            const float* w2 = Wr2 + (size_t)(n0 + tid) * NE;
#pragma unroll
            for (int e = 0; e < NE; e++) l[e] = h * w2[e];
#pragma unroll
            for (int off = 16; off > 0; off >>= 1)
#pragma unroll
                for (int e = 0; e < NE; e++) l[e] += __shfl_xor_sync(0xffffffffu, l[e], off);
            if ((tid & 31) == 0)
#pragma unroll
                for (int e = 0; e < NE; e++) lred[tid >> 5][e] = l[e];
        }
        __syncthreads();
        if (tid == 0) {
#pragma unroll
            for (int e = 0; e < NE; e++)
                g_plog[((size_t)si * 8 + blockIdx.x) * NE + e] =
                    (lred[0][e] + lred[1][e]) + (lred[2][e] + lred[3][e]);
        }
        __syncthreads();
    }
}

// Phase B: sum the 8 chunk-partials in fixed order, argmax, correct g_chosen.
__global__ __launch_bounds__(256)
void fixup_resolve(const float* __restrict__ br2)
{
    int si = blockIdx.x * blockDim.x + threadIdx.x;
    if (si >= g_nsus) return;
    float lg[NE];
#pragma unroll
    for (int e = 0; e < NE; e++) lg[e] = br2[e];
#pragma unroll
    for (int c = 0; c < 8; c++)
#pragma unroll
        for (int e = 0; e < NE; e++)
            lg[e] += g_plog[((size_t)si * 8 + c) * NE + e];
    int best = 0;
    float bv = lg[0];
#pragma unroll
    for (int e = 1; e < NE; e++)
        if (lg[e] > bv) { bv = lg[e]; best = e; }
    g_chosen[g_suspects[si]] = best;
}

__global__ void count_tokens()
{
    int t = blockIdx.x * blockDim.x + threadIdx.x;
    if (t < N_TOK) atomicAdd(&g_counts[g_chosen[t]], 1);
}

__global__ void scan_offsets()
{
    if (threadIdx.x == 0 && blockIdx.x == 0) {
        int o = 0;
        for (int e = 0; e < NE; e++) {
            g_offsets[e] = o;
            g_cursor[e] = o;
            o += g_counts[e];
        }
        g_offsets[NE] = o;
    }
}

__global__ void scatter_tokens()
{
    int t = blockIdx.x * blockDim.x + threadIdx.x;
    if (t >= N_TOK) return;
    int e = g_chosen[t];
    int pos = atomicAdd(&g_cursor[e], 1);
    g_perm[pos] = t;
}

// ---------------- launch ----------------
extern "C" void kernel_launch(void* const* d_in, const int* in_sizes, int n_in,
                              void* d_out, int out_size)
{
    const float* x   = (const float*)d_in[0];
    const float* Wr1 = (const float*)d_in[1];
    const float* br1 = (const float*)d_in[2];
    const float* Wr2 = (const float*)d_in[3];
    const float* br2 = (const float*)d_in[4];
    const float* W1  = (const float*)d_in[5];
    const float* b1  = (const float*)d_in[6];
    const float* W2  = (const float*)d_in[7];
    const float* b2  = (const float*)d_in[8];
    float* out = (float*)d_out;

    auto* kRouter = ffn_mma<EMB, EMB, false, false, true, false, 0, 2>;
    auto* kFfn1   = ffn_mma<HID, EMB, true, true, true, false, 0, 1>;
    auto* kFfn2   = ffn_mma<EMB, HID, true, false, false, true, 1, 0>;
    cudaFuncSetAttribute(kRouter, cudaFuncAttributeMaxDynamicSharedMemorySize, FFN_SMEM);
    cudaFuncSetAttribute(kFfn1, cudaFuncAttributeMaxDynamicSharedMemorySize, FFN_SMEM);
    cudaFuncSetAttribute(kFfn2, cudaFuncAttributeMaxDynamicSharedMemorySize, FFN_SMEM);

    init_counts<<<1, 32>>>();
    kRouter<<<dim3(N_TOK / 128, EMB / 256, 1), 256, FFN_SMEM>>>(x, Wr1, br1, nullptr);
    router_argmax<<<(N_TOK * 32) / 256, 256>>>(Wr2, br2);
    fixup_partial<<<dim3(8, 256), 256>>>(x, Wr1, br1, Wr2);
    fixup_resolve<<<N_TOK / 256, 256>>>(br2);
    count_tokens<<<N_TOK / 256, 256>>>();
    scan_offsets<<<1, 1>>>();
    scatter_tokens<<<N_TOK / 256, 256>>>();
    kFfn1<<<dim3(N_TOK / 128, HID / 256, NE), 256, FFN_SMEM>>>(x, W1, b1, nullptr);
    kFfn2<<<dim3(N_TOK / 128, EMB / 256, NE), 256, FFN_SMEM>>>(nullptr, W2, b2, out);
}